// round 7
// baseline (speedup 1.0000x reference)
#include <cuda_runtime.h>
#include <cstdint>

// LSTMDecoder: B=1024, A=H=16, R=128, T=128.
// 16 threads per batch element; lane j owns h_j, c_j and 4 gate rows of W_hh.
// R6 change: packed fma.rn.f32x2 for the gate dots. Gates packed as (i,f) and
// (g,o) pairs; weights pre-packed; h duplicated via mov.b64 (ALU pipe).
// fma-pipe ops per cell: 64 FFMA -> 32 FFMA2 + 2 ADD2.

#define NT 128

__device__ __forceinline__ float tanhapx(float x) {
    float r;
    asm("tanh.approx.f32 %0, %1;" : "=f"(r) : "f"(x));
    return r;
}
__device__ __forceinline__ float sigapx(float x) {
    return fmaf(0.5f, tanhapx(0.5f * x), 0.5f);
}
__device__ __forceinline__ uint64_t pack2(float lo, float hi) {
    uint64_t r;
    asm("mov.b64 %0, {%1, %2};" : "=l"(r) : "f"(lo), "f"(hi));
    return r;
}
__device__ __forceinline__ void unpack2(float& lo, float& hi, uint64_t v) {
    asm("mov.b64 {%0, %1}, %2;" : "=f"(lo), "=f"(hi) : "l"(v));
}
__device__ __forceinline__ void fma2(uint64_t& d, uint64_t a, uint64_t b) {
    asm("fma.rn.f32x2 %0, %1, %2, %0;" : "+l"(d) : "l"(a), "l"(b));
}
__device__ __forceinline__ uint64_t add2(uint64_t a, uint64_t b) {
    uint64_t r;
    asm("add.rn.f32x2 %0, %1, %2;" : "=l"(r) : "l"(a), "l"(b));
    return r;
}

__global__ __launch_bounds__(128, 1)
void lstm_decoder_kernel(
    const float* __restrict__ y,     // (B,16)
    const float* __restrict__ u,     // (B,128)
    const float* __restrict__ W_ih,  // (64,1)
    const float* __restrict__ W_hh,  // (64,16)
    const float* __restrict__ b_ih,  // (64)
    const float* __restrict__ b_hh,  // (64)
    const float* __restrict__ W_lin, // (1,16)
    const float* __restrict__ b_lin, // (1)
    const float* __restrict__ W_h0,  // (16,128)
    const float* __restrict__ b_h0,  // (16)
    const float* __restrict__ W_c0,  // (16,128)
    const float* __restrict__ b_c0,  // (16)
    float* __restrict__ out)         // (B,144)
{
    const int tid = blockIdx.x * blockDim.x + threadIdx.x;
    const int b   = tid >> 4;     // batch element
    const int j   = tid & 15;     // hidden index
    const unsigned FULL = 0xffffffffu;

    // ---- per-thread packed weight pairs: (i,f) and (g,o) per k ----
    uint64_t Wif[16], Wgo[16];
#pragma unroll
    for (int k = 0; k < 16; k++) {
        Wif[k] = pack2(W_hh[(     j) * 16 + k], W_hh[(16 + j) * 16 + k]);
        Wgo[k] = pack2(W_hh[(32 + j) * 16 + k], W_hh[(48 + j) * 16 + k]);
    }
    const uint64_t win_if = pack2(W_ih[j],      W_ih[16 + j]);
    const uint64_t win_go = pack2(W_ih[32 + j], W_ih[48 + j]);
    const uint64_t b_if = pack2(b_ih[j]      + b_hh[j],
                                b_ih[16 + j] + b_hh[16 + j]);
    const uint64_t b_go = pack2(b_ih[32 + j] + b_hh[32 + j],
                                b_ih[48 + j] + b_hh[48 + j]);
    const float wl = W_lin[j];
    const float bl = b_lin[0];

    // ---- h0 = u @ W_h0.T + b_h0 ; c0 = u @ W_c0.T + b_c0 ----
    float h = b_h0[j];
    float c = b_c0[j];
    {
        const float4* u4  = (const float4*)(u    + b * 128);
        const float4* wh4 = (const float4*)(W_h0 + j * 128);
        const float4* wc4 = (const float4*)(W_c0 + j * 128);
#pragma unroll 4
        for (int r = 0; r < 32; r++) {
            float4 uu = u4[r], wh = wh4[r], wc = wc4[r];
            h = fmaf(uu.x, wh.x, h); h = fmaf(uu.y, wh.y, h);
            h = fmaf(uu.z, wh.z, h); h = fmaf(uu.w, wh.w, h);
            c = fmaf(uu.x, wc.x, c); c = fmaf(uu.y, wc.y, c);
            c = fmaf(uu.z, wc.z, c); c = fmaf(uu.w, wc.w, c);
        }
    }

    // ---- window replicated per-thread: xs[s] = window[:, s] ----
    float xs[16];
    {
        const float4* y4 = (const float4*)(y + b * 16);
        float4 y0 = y4[0], y1 = y4[1], y2 = y4[2], y3 = y4[3];
        xs[0]=y0.x; xs[1]=y0.y; xs[2]=y0.z; xs[3]=y0.w;
        xs[4]=y1.x; xs[5]=y1.y; xs[6]=y1.z; xs[7]=y1.w;
        xs[8]=y2.x; xs[9]=y2.y; xs[10]=y2.z; xs[11]=y2.w;
        xs[12]=y3.x; xs[13]=y3.y; xs[14]=y3.z; xs[15]=y3.w;
    }
    out[b * 144 + j] = y[b * 16 + j];        // first 16 output cols = y
    float* outp = out + b * 144 + 16;

    for (int t = 0; t < NT; t++) {
        // 16 sequential LSTM cells over window (fully unrolled; xs static)
#pragma unroll
        for (int s = 0; s < 16; s++) {
            // x-dependent init is off the critical path (xs known early)
            uint64_t xd = pack2(xs[s], xs[s]);
            uint64_t aif0 = b_if, aif1 = 0ull;
            uint64_t ago0 = b_go, ago1 = 0ull;
            fma2(aif0, xd, win_if);
            fma2(ago0, xd, win_go);
#pragma unroll
            for (int k = 0; k < 16; k += 2) {
                float h0 = __shfl_sync(FULL, h, k,     16);
                float h1 = __shfl_sync(FULL, h, k + 1, 16);
                uint64_t hd0 = pack2(h0, h0);
                uint64_t hd1 = pack2(h1, h1);
                fma2(aif0, hd0, Wif[k]);
                fma2(ago0, hd0, Wgo[k]);
                fma2(aif1, hd1, Wif[k + 1]);
                fma2(ago1, hd1, Wgo[k + 1]);
            }
            float ai, af, ag, ao;
            unpack2(ai, af, add2(aif0, aif1));
            unpack2(ag, ao, add2(ago0, ago1));
            float ig = sigapx(ai);
            float fg = sigapx(af);
            float gg = tanhapx(ag);
            float og = sigapx(ao);
            c = fmaf(fg, c, ig * gg);
            h = og * tanhapx(c);
        }
        // pred = sum_j h_j * W_lin_j + b_lin (feeds xs[15], consumed 15 cells
        // later -> off the critical path)
        float p = h * wl;
#pragma unroll
        for (int off = 8; off; off >>= 1)
            p += __shfl_xor_sync(FULL, p, off, 16);
        p += bl;

        if (j == 0) outp[t] = p;

#pragma unroll
        for (int s = 0; s < 15; s++) xs[s] = xs[s + 1];
        xs[15] = p;
    }
}

extern "C" void kernel_launch(void* const* d_in, const int* in_sizes, int n_in,
                              void* d_out, int out_size) {
    const float* y     = (const float*)d_in[0];
    const float* u     = (const float*)d_in[1];
    const float* W_ih  = (const float*)d_in[2];
    const float* W_hh  = (const float*)d_in[3];
    const float* b_ih  = (const float*)d_in[4];
    const float* b_hh  = (const float*)d_in[5];
    const float* W_lin = (const float*)d_in[6];
    const float* b_lin = (const float*)d_in[7];
    const float* W_h0  = (const float*)d_in[8];
    const float* b_h0  = (const float*)d_in[9];
    const float* W_c0  = (const float*)d_in[10];
    const float* b_c0  = (const float*)d_in[11];
    float* out = (float*)d_out;

    lstm_decoder_kernel<<<128, 128>>>(y, u, W_ih, W_hh, b_ih, b_hh,
                                      W_lin, b_lin, W_h0, b_h0, W_c0, b_c0, out);
}